// round 6
// baseline (speedup 1.0000x reference)
#include <cuda_runtime.h>

// FFM layer: out[b] = sigmoid( linear(b) + 0.5*sum_k((sum_g f)^2 - sum_g f^2) )
// f[b,g,k] = sum_d dense_x[b,d]*v[d,g,k] + sum_i v[idx[b,i],g,k]
//
// Inputs (metadata order):
//  d_in[0] dense_x  f32 [B,13]
//  d_in[1] sparse_x i32 [B,26]
//  d_in[2] W        f32 [26013]
//  d_in[3] b        f32 [1]
//  d_in[4] v        f32 [26013,39,8]
// Output: f32 [B]

namespace {
constexpr int N_DENSE  = 13;
constexpr int N_SPARSE = 26;
constexpr int ONEHOT   = 1000;
constexpr int KDIM     = 8;
constexpr int FIELDS   = N_DENSE + N_SPARSE;   // 39
constexpr int ROW      = FIELDS * KDIM;        // 312 floats per v row
constexpr int SPB      = 32;                   // samples per block
constexpr int THREADS  = SPB * KDIM;           // 256
}

__global__ __launch_bounds__(THREADS) void ffm_kernel(
    const float* __restrict__ dense_x,
    const int*   __restrict__ sparse_x,
    const float* __restrict__ W,
    const float* __restrict__ bias,
    const float* __restrict__ v,
    float*       __restrict__ out,
    int B)
{
    __shared__ float s_vd[N_DENSE * ROW];        // 4056 floats = 16224 B
    __shared__ float s_dx[SPB][N_DENSE];
    __shared__ int   s_idx[SPB][N_SPARSE];

    const int tid = threadIdx.x;
    const int b0  = blockIdx.x * SPB;

    // Stage dense slice of v (shared by every sample) into smem, vectorized.
    {
        const float4* v4  = reinterpret_cast<const float4*>(v);
        float4*       sv4 = reinterpret_cast<float4*>(s_vd);
        #pragma unroll
        for (int i = tid; i < (N_DENSE * ROW) / 4; i += THREADS)
            sv4[i] = v4[i];
    }
    // Stage dense_x for this block's 32 samples.
    for (int i = tid; i < SPB * N_DENSE; i += THREADS) {
        int s = i / N_DENSE, d = i % N_DENSE;
        int b = b0 + s;
        s_dx[s][d] = (b < B) ? dense_x[b * N_DENSE + d] : 0.0f;
    }
    // Stage global one-hot row indices.
    for (int i = tid; i < SPB * N_SPARSE; i += THREADS) {
        int s = i / N_SPARSE, f = i % N_SPARSE;
        int b = b0 + s;
        s_idx[s][f] = (b < B) ? (N_DENSE + f * ONEHOT + sparse_x[b * N_SPARSE + f])
                              : N_DENSE;   // harmless in-range dummy
    }
    __syncthreads();

    const int s = tid >> 3;   // sample within block
    const int k = tid & 7;    // latent lane owned by this thread
    const int b = b0 + s;

    float f[FIELDS];
    #pragma unroll
    for (int g = 0; g < FIELDS; ++g) f[g] = 0.0f;

    // Dense contribution: f[g] += sum_d x_d * v[d,g,k]  (smem, conflict-free)
    #pragma unroll
    for (int d = 0; d < N_DENSE; ++d) {
        const float xd = s_dx[s][d];
        const float* vd = &s_vd[d * ROW + k];
        #pragma unroll
        for (int g = 0; g < FIELDS; ++g)
            f[g] = fmaf(xd, vd[g * KDIM], f[g]);
    }

    // Sparse gathers: 26 random rows; 8-thread group reads one 32B sector per
    // (row,g); inner loop fully unrolled for MLP, outer loop rolled to keep
    // code size sane.
    #pragma unroll 1
    for (int i = 0; i < N_SPARSE; ++i) {
        const float* row = v + (size_t)s_idx[s][i] * ROW + k;
        #pragma unroll
        for (int g = 0; g < FIELDS; ++g)
            f[g] += __ldg(row + g * KDIM);
    }

    // Per-k interaction partial: 0.5 * ((sum_g f)^2 - sum_g f^2)
    float ssum = 0.0f, sqsum = 0.0f;
    #pragma unroll
    for (int g = 0; g < FIELDS; ++g) {
        ssum += f[g];
        sqsum = fmaf(f[g], f[g], sqsum);
    }
    float part = 0.5f * (ssum * ssum - sqsum);

    // Linear partials distributed over the 8 lanes of this sample.
    for (int i = k; i < N_SPARSE; i += KDIM)
        part += __ldg(W + s_idx[s][i]);
    for (int d = k; d < N_DENSE; d += KDIM)
        part += s_dx[s][d] * __ldg(W + d);

    // Reduce across the 8-lane subgroup.
    part += __shfl_down_sync(0xffffffffu, part, 4, 8);
    part += __shfl_down_sync(0xffffffffu, part, 2, 8);
    part += __shfl_down_sync(0xffffffffu, part, 1, 8);

    if (k == 0 && b < B) {
        float z = part + __ldg(bias);
        out[b] = 1.0f / (1.0f + expf(-z));
    }
}

extern "C" void kernel_launch(void* const* d_in, const int* in_sizes, int n_in,
                              void* d_out, int out_size)
{
    const float* dense_x  = (const float*)d_in[0];
    const int*   sparse_x = (const int*)  d_in[1];
    const float* W        = (const float*)d_in[2];
    const float* bias     = (const float*)d_in[3];
    const float* v        = (const float*)d_in[4];
    float*       out      = (float*)d_out;

    const int B = in_sizes[0] / N_DENSE;
    const int grid = (B + SPB - 1) / SPB;
    ffm_kernel<<<grid, THREADS>>>(dense_x, sparse_x, W, bias, v, out, B);
}

// round 7
// speedup vs baseline: 1.0008x; 1.0008x over previous
#include <cuda_runtime.h>

// FFM layer: out[b] = sigmoid( linear(b) + 0.5*sum_k((sum_g f)^2 - sum_g f^2) )
// f[b,g,k] = sum_d dense_x[b,d]*v[d,g,k] + sum_i v[idx[b,i],g,k]
//
// Inputs (metadata order):
//  d_in[0] dense_x  f32 [B,13]
//  d_in[1] sparse_x i32 [B,26]
//  d_in[2] W        f32 [26013]
//  d_in[3] b        f32 [1]
//  d_in[4] v        f32 [26013,39,8]
// Output: f32 [B]

namespace {
constexpr int N_DENSE  = 13;
constexpr int N_SPARSE = 26;
constexpr int ONEHOT   = 1000;
constexpr int KDIM     = 8;
constexpr int FIELDS   = N_DENSE + N_SPARSE;   // 39
constexpr int ROW      = FIELDS * KDIM;        // 312 floats per v row
constexpr int SPB      = 32;                   // samples per block
constexpr int THREADS  = SPB * KDIM;           // 256
}

__global__ __launch_bounds__(THREADS) void ffm_kernel(
    const float* __restrict__ dense_x,
    const int*   __restrict__ sparse_x,
    const float* __restrict__ W,
    const float* __restrict__ bias,
    const float* __restrict__ v,
    float*       __restrict__ out,
    int B)
{
    __shared__ float s_vd[N_DENSE * ROW];        // 4056 floats = 16224 B
    __shared__ float s_dx[SPB][N_DENSE];
    __shared__ int   s_idx[SPB][N_SPARSE];

    const int tid = threadIdx.x;
    const int b0  = blockIdx.x * SPB;

    // Stage dense slice of v (shared by every sample) into smem, vectorized.
    {
        const float4* v4  = reinterpret_cast<const float4*>(v);
        float4*       sv4 = reinterpret_cast<float4*>(s_vd);
        #pragma unroll
        for (int i = tid; i < (N_DENSE * ROW) / 4; i += THREADS)
            sv4[i] = v4[i];
    }
    // Stage dense_x for this block's 32 samples.
    for (int i = tid; i < SPB * N_DENSE; i += THREADS) {
        int s = i / N_DENSE, d = i % N_DENSE;
        int b = b0 + s;
        s_dx[s][d] = (b < B) ? dense_x[b * N_DENSE + d] : 0.0f;
    }
    // Stage global one-hot row indices.
    for (int i = tid; i < SPB * N_SPARSE; i += THREADS) {
        int s = i / N_SPARSE, f = i % N_SPARSE;
        int b = b0 + s;
        s_idx[s][f] = (b < B) ? (N_DENSE + f * ONEHOT + sparse_x[b * N_SPARSE + f])
                              : N_DENSE;   // harmless in-range dummy
    }
    __syncthreads();

    const int s = tid >> 3;   // sample within block
    const int k = tid & 7;    // latent lane owned by this thread
    const int b = b0 + s;

    float f[FIELDS];
    #pragma unroll
    for (int g = 0; g < FIELDS; ++g) f[g] = 0.0f;

    // Dense contribution: f[g] += sum_d x_d * v[d,g,k]  (smem, conflict-free)
    #pragma unroll
    for (int d = 0; d < N_DENSE; ++d) {
        const float xd = s_dx[s][d];
        const float* vd = &s_vd[d * ROW + k];
        #pragma unroll
        for (int g = 0; g < FIELDS; ++g)
            f[g] = fmaf(xd, vd[g * KDIM], f[g]);
    }

    // Sparse gathers: 26 random rows; 8-thread group reads one 32B sector per
    // (row,g); inner loop fully unrolled for MLP, outer loop rolled to keep
    // code size sane.
    #pragma unroll 1
    for (int i = 0; i < N_SPARSE; ++i) {
        const float* row = v + (size_t)s_idx[s][i] * ROW + k;
        #pragma unroll
        for (int g = 0; g < FIELDS; ++g)
            f[g] += __ldg(row + g * KDIM);
    }

    // Per-k interaction partial: 0.5 * ((sum_g f)^2 - sum_g f^2)
    float ssum = 0.0f, sqsum = 0.0f;
    #pragma unroll
    for (int g = 0; g < FIELDS; ++g) {
        ssum += f[g];
        sqsum = fmaf(f[g], f[g], sqsum);
    }
    float part = 0.5f * (ssum * ssum - sqsum);

    // Linear partials distributed over the 8 lanes of this sample.
    for (int i = k; i < N_SPARSE; i += KDIM)
        part += __ldg(W + s_idx[s][i]);
    for (int d = k; d < N_DENSE; d += KDIM)
        part += s_dx[s][d] * __ldg(W + d);

    // Reduce across the 8-lane subgroup.
    part += __shfl_down_sync(0xffffffffu, part, 4, 8);
    part += __shfl_down_sync(0xffffffffu, part, 2, 8);
    part += __shfl_down_sync(0xffffffffu, part, 1, 8);

    if (k == 0 && b < B) {
        float z = part + __ldg(bias);
        out[b] = 1.0f / (1.0f + expf(-z));
    }
}

extern "C" void kernel_launch(void* const* d_in, const int* in_sizes, int n_in,
                              void* d_out, int out_size)
{
    const float* dense_x  = (const float*)d_in[0];
    const int*   sparse_x = (const int*)  d_in[1];
    const float* W        = (const float*)d_in[2];
    const float* bias     = (const float*)d_in[3];
    const float* v        = (const float*)d_in[4];
    float*       out      = (float*)d_out;

    const int B = in_sizes[0] / N_DENSE;
    const int grid = (B + SPB - 1) / SPB;
    ffm_kernel<<<grid, THREADS>>>(dense_x, sparse_x, W, bias, v, out, B);
}